// round 4
// baseline (speedup 1.0000x reference)
#include <cuda_runtime.h>
#include <cuda_fp16.h>
#include <mma.h>
#include <stdint.h>

using namespace nvcuda;

// Problem dims
#define BATCH   256
#define TSEQ    1024
#define IN_D    128
#define HID     256
#define OUT_D   128

// Partitioning: 16 batch-groups x 8 unit-groups; the 8 unit-group CTAs form one cluster
#define NBG     16
#define NUG     8
#define MB      16            // batch rows per CTA (and per batch group)
#define UPC     32            // hidden units per CTA
#define NGATE   4
#define NROWS   (UPC*NGATE)   // 128 gate rows per CTA
#define KDIM    (HID + IN_D)  // 384 combined K  [h | x]
#define KPAD    392           // padded K stride (halves)
#define ZPAD    132           // padded z stride (floats)
#define NTHREADS 256
#define KSTEPS  (KDIM/16)     // 24

#define SW_ELEMS (NROWS*KPAD)           // 50176 halves
#define SA_ELEMS (MB*KPAD)              // 6272 halves (one A tile)
#define SZ_ELEMS (MB*ZPAD)              // 2112 floats
#define SH_ELEMS (MB*UPC)               // 512 halves (local h staging)
#define SMEM_BYTES (SW_ELEMS*2 + 2*SA_ELEMS*2 + SZ_ELEMS*4 + NROWS*4 + SH_ELEMS*2)

// fp32 h_T for the final projection (written once at t=TSEQ-1)
__device__ float g_h32[BATCH*HID];

__device__ __forceinline__ float tanh_fast(float x) {
    float e = __expf(2.0f * x);
    return 1.0f - 2.0f / (e + 1.0f);
}
__device__ __forceinline__ float sigm_fast(float x) {
    return 1.0f / (1.0f + __expf(-x));
}

__global__ void __launch_bounds__(NTHREADS, 1) __cluster_dims__(NUG, 1, 1)
lstm_main_kernel(const float* __restrict__ x,
                 const float* __restrict__ Wgx, const float* __restrict__ bgx, const float* __restrict__ Wgh,
                 const float* __restrict__ Wix, const float* __restrict__ bix, const float* __restrict__ Wih,
                 const float* __restrict__ Wfx, const float* __restrict__ bfx, const float* __restrict__ Wfh,
                 const float* __restrict__ Wox, const float* __restrict__ boxp, const float* __restrict__ Woh,
                 const float* __restrict__ Wp, const float* __restrict__ bp,
                 float* __restrict__ out)
{
    extern __shared__ unsigned char smem_raw[];
    __half* sW    = (__half*)smem_raw;                 // [NROWS][KPAD]
    __half* sA    = sW + SW_ELEMS;                     // [2][MB][KPAD]  (h | x_t), double buffered
    float*  sZ    = (float*)(sA + 2*SA_ELEMS);         // [MB][ZPAD]
    float*  sBias = sZ + SZ_ELEMS;                     // [NROWS]
    __half* sH    = (__half*)(sBias + NROWS);          // [MB][UPC] local h staging

    const int tid  = threadIdx.x;
    const int warp = tid >> 5;
    const int ug   = blockIdx.x % NUG;    // == cluster rank
    const int bg   = blockIdx.x / NUG;

    // ---- Load weight slice into smem fp16: row n = gate*32+u, cols [Wh(256)|Wx(128)] ----
    {
        const float* WhA[4] = {Wgh, Wih, Wfh, Woh};
        const float* WxA[4] = {Wgx, Wix, Wfx, Wox};
        #pragma unroll
        for (int g = 0; g < 4; ++g) {
            const float* wh = WhA[g];
            const float* wx = WxA[g];
            for (int idx = tid; idx < UPC*KDIM; idx += NTHREADS) {
                int ul = idx / KDIM;
                int k  = idx - ul*KDIM;
                int n  = g*UPC + ul;
                int ugl = ug*UPC + ul;
                float w = (k < HID) ? wh[ugl*HID + k] : wx[ugl*IN_D + (k - HID)];
                sW[n*KPAD + k] = __float2half_rn(w);
            }
        }
        if (tid < UPC) {
            const float* bxA[4] = {bgx, bix, bfx, boxp};
            #pragma unroll
            for (int g = 0; g < 4; ++g)
                sBias[g*UPC + tid] = bxA[g][ug*UPC + tid];
        }
    }

    // ---- Init A buffer 0: h region = 0, x region = x_0 ----
    {
        // zero h region (16 rows x 256 halves = 2048 u32 words)
        for (int i = tid; i < MB*HID/2; i += NTHREADS) {
            int row = i >> 7;            // /128 words per row
            int w2  = i & 127;
            *(uint32_t*)&sA[row*KPAD + w2*2] = 0u;
        }
        // x_0
        #pragma unroll
        for (int j = 0; j < 2; ++j) {
            int cc  = tid + (j << 8);
            int row = cc >> 5;
            int c4  = cc & 31;
            float4 v = *(const float4*)&x[(bg*MB + row)*(TSEQ*IN_D) + 0*IN_D + c4*4];
            __half2* d = (__half2*)&sA[row*KPAD + HID + c4*4];
            d[0] = __floats2half2_rn(v.x, v.y);
            d[1] = __floats2half2_rn(v.z, v.w);
        }
    }
    __syncthreads();

    // ---- Load all B fragments into registers (loop-invariant weights) ----
    wmma::fragment<wmma::matrix_a, 16,16,16, __half, wmma::row_major> fa;
    wmma::fragment<wmma::matrix_b, 16,16,16, __half, wmma::col_major> fbr[KSTEPS];
    wmma::fragment<wmma::accumulator, 16,16,16, float> fc;
    const int n0 = warp * 16;
    #pragma unroll
    for (int kk = 0; kk < KSTEPS; ++kk)
        wmma::load_matrix_sync(fbr[kk], sW + n0*KPAD + kk*16, KPAD);

    // per-thread cell state: thread (b0, uu) handles rows b0 and b0+8 of its unit uu
    const int b0 = tid >> 5;
    const int uu = tid & 31;
    float c0 = 0.0f, c1 = 0.0f;

    // precompute DSMEM destination base offsets (byte address of sA in shared window)
    const uint32_t sa_base_u32 = (uint32_t)__cvta_generic_to_shared(sA);

    for (int t = 0; t < TSEQ; ++t) {
        const int p = t & 1;

        // ---- Prefetch x_{t+1} into registers (hidden under the GEMM) ----
        float4 xv0, xv1;
        {
            int tn  = (t + 1 < TSEQ) ? (t + 1) : t;
            int row = tid >> 4;
            int q   = (tid & 15) * 8;
            const float* src = &x[(bg*MB + row)*(TSEQ*IN_D) + tn*IN_D + q];
            xv0 = *(const float4*)src;
            xv1 = *(const float4*)(src + 4);
        }

        // ---- GEMM: z[16 x 128] = A[16 x 384] @ W^T, B in registers ----
        const __half* sAp = sA + p*SA_ELEMS;
        wmma::fill_fragment(fc, 0.0f);
        #pragma unroll
        for (int kk = 0; kk < KSTEPS; ++kk) {
            wmma::load_matrix_sync(fa, sAp + kk*16, KPAD);
            wmma::mma_sync(fc, fa, fbr[kk], fc);
        }
        wmma::store_matrix_sync(sZ + n0, fc, ZPAD, wmma::mem_row_major);
        __syncthreads();

        // ---- Epilogue: gates, c/h update -> local staging ----
        #pragma unroll
        for (int j = 0; j < 2; ++j) {
            int b = b0 + j*8;
            const float* zr = &sZ[b*ZPAD];
            float zg = zr[uu]          + sBias[uu];
            float zi = zr[UPC   + uu]  + sBias[UPC   + uu];
            float zf = zr[2*UPC + uu]  + sBias[2*UPC + uu];
            float zo = zr[3*UPC + uu]  + sBias[3*UPC + uu];
            float gv = tanh_fast(zg);
            float iv = sigm_fast(zi);
            float fv = sigm_fast(zf);
            float ov = sigm_fast(zo);
            float& c = j ? c1 : c0;
            c = gv*iv + c*fv;
            float h = tanh_fast(c) * ov;
            sH[b*UPC + uu] = __float2half_rn(h);
            if (t == TSEQ-1) g_h32[(bg*MB + b)*HID + ug*UPC + uu] = h;
        }
        __syncthreads();

        // ---- Push local h slice into all 8 cluster CTAs' next A buffer (DSMEM) ----
        {
            int row  = tid >> 4;                 // 0..15
            int c2   = (tid & 15) * 2;           // half pair within the 32-unit slice
            uint32_t val = ((const uint32_t*)sH)[tid];
            uint32_t dst_local = sa_base_u32 +
                (uint32_t)(((p ^ 1)*SA_ELEMS + row*KPAD + ug*UPC + c2) * 2);
            #pragma unroll
            for (int r = 0; r < NUG; ++r) {
                uint32_t remote;
                asm volatile("mapa.shared::cluster.u32 %0, %1, %2;"
                             : "=r"(remote) : "r"(dst_local), "r"(r));
                asm volatile("st.shared::cluster.u32 [%0], %1;"
                             :: "r"(remote), "r"(val) : "memory");
            }
        }

        // ---- Cluster barrier; overlap x_{t+1} smem store with barrier skew ----
        asm volatile("barrier.cluster.arrive.aligned;" ::: "memory");
        {
            int row = tid >> 4;
            int q   = (tid & 15) * 8;
            __half2 h0 = __floats2half2_rn(xv0.x, xv0.y);
            __half2 h1 = __floats2half2_rn(xv0.z, xv0.w);
            __half2 h2 = __floats2half2_rn(xv1.x, xv1.y);
            __half2 h3 = __floats2half2_rn(xv1.z, xv1.w);
            uint4 pk;
            pk.x = *(uint32_t*)&h0; pk.y = *(uint32_t*)&h1;
            pk.z = *(uint32_t*)&h2; pk.w = *(uint32_t*)&h3;
            *(uint4*)&sA[(p ^ 1)*SA_ELEMS + row*KPAD + HID + q] = pk;
        }
        asm volatile("barrier.cluster.wait.aligned;" ::: "memory");
    }

    // ---- Final projection: out = h_T @ Wp^T + bp (fp32), ug==0 CTAs only ----
    if (ug == 0) {
        const int b     = tid >> 4;
        const int obase = (tid & 15) * 8;
        float acc[8];
        #pragma unroll
        for (int r = 0; r < 8; ++r) acc[r] = bp[obase + r];
        const float* hrow = &g_h32[(bg*MB + b)*HID];
        for (int k = 0; k < HID; ++k) {
            float hv = hrow[k];
            #pragma unroll
            for (int r = 0; r < 8; ++r)
                acc[r] = fmaf(hv, Wp[(obase + r)*HID + k], acc[r]);
        }
        #pragma unroll
        for (int r = 0; r < 8; ++r)
            out[(bg*MB + b)*OUT_D + obase + r] = acc[r];
    }
}

extern "C" void kernel_launch(void* const* d_in, const int* in_sizes, int n_in,
                              void* d_out, int out_size) {
    const float* x   = (const float*)d_in[0];
    const float* Wgx = (const float*)d_in[1];
    const float* bgx = (const float*)d_in[2];
    const float* Wgh = (const float*)d_in[3];
    const float* Wix = (const float*)d_in[4];
    const float* bix = (const float*)d_in[5];
    const float* Wih = (const float*)d_in[6];
    const float* Wfx = (const float*)d_in[7];
    const float* bfx = (const float*)d_in[8];
    const float* Wfh = (const float*)d_in[9];
    const float* Wox = (const float*)d_in[10];
    const float* box = (const float*)d_in[11];
    const float* Woh = (const float*)d_in[12];
    const float* Wp  = (const float*)d_in[13];
    const float* bp  = (const float*)d_in[14];
    float* out = (float*)d_out;

    static bool attr_set = false;
    if (!attr_set) {
        cudaFuncSetAttribute(lstm_main_kernel,
                             cudaFuncAttributeMaxDynamicSharedMemorySize, SMEM_BYTES);
        attr_set = true;
    }

    lstm_main_kernel<<<NBG*NUG, NTHREADS, SMEM_BYTES>>>(
        x, Wgx, bgx, Wgh, Wix, bix, Wih, Wfx, bfx, Wfh, Wox, box, Woh, Wp, bp, out);
}